// round 1
// baseline (speedup 1.0000x reference)
#include <cuda_runtime.h>
#include <cuda_bf16.h>

#define TT 512
#define MM 16
#define PP 600
#define BB 32

__device__ __forceinline__ float ex2(float v) {
    float r;
    asm("ex2.approx.ftz.f32 %0, %1;" : "=f"(r) : "f"(v));
    return r;
}

__global__ __launch_bounds__(64) void func_repr_kernel(
    const float* __restrict__ y, const float* __restrict__ x,
    const int*   __restrict__ mask, const float* __restrict__ sigma,
    float* __restrict__ out)
{
    extern __shared__ float sm[];
    float* sx = sm;                 // [TT]
    float* sy = sm + TT;            // [MM][TT]
    float* sk = sm + TT + MM * TT;  // [MM][TT] mask as float

    const int b   = blockIdx.y;
    const int tid = threadIdx.x;

    // ---- cooperative stage: x, y, mask(int->float), all float4 coalesced ----
    {
        const float4* xg = (const float4*)(x + (size_t)b * TT);
        for (int i = tid; i < TT / 4; i += 64) ((float4*)sx)[i] = xg[i];

        const float4* yg = (const float4*)(y    + (size_t)b * MM * TT);
        const int4*   mg = (const int4*)  (mask + (size_t)b * MM * TT);
        #pragma unroll 4
        for (int i = tid; i < MM * TT / 4; i += 64) {
            ((float4*)sy)[i] = yg[i];
            int4 mv = mg[i];
            ((float4*)sk)[i] = make_float4((float)mv.x, (float)mv.y,
                                           (float)mv.z, (float)mv.w);
        }
    }
    __syncthreads();

    const int   p = blockIdx.x * 64 + tid;
    const float g = fmaf((float)p, 50.0f / 599.0f, -1.0f);

    const float s0 = sigma[0], s1 = sigma[1];
    const float LOG2E = 1.4426950408889634f;
    const float c0 = 0.5f * LOG2E / (s0 * s0);   // exp(-d2*inv) == ex2(-d2*c)
    const float c1 = 0.5f * LOG2E / (s1 * s1);

    float accd[MM], accc[MM];
    #pragma unroll
    for (int m = 0; m < MM; m++) { accd[m] = 0.f; accc[m] = 0.f; }

    for (int t = 0; t < TT; t += 4) {
        float4 xv = *(const float4*)(sx + t);          // LDS.128 broadcast
        float dx0 = g - xv.x, dx1 = g - xv.y, dx2 = g - xv.z, dx3 = g - xv.w;
        float d0 = dx0 * dx0, d1 = dx1 * dx1, d2 = dx2 * dx2, d3 = dx3 * dx3;
        float w00 = ex2(-d0 * c0), w01 = ex2(-d1 * c0),
              w02 = ex2(-d2 * c0), w03 = ex2(-d3 * c0);
        float w10 = ex2(-d0 * c1), w11 = ex2(-d1 * c1),
              w12 = ex2(-d2 * c1), w13 = ex2(-d3 * c1);

        #pragma unroll
        for (int m = 0; m < MM; m++) {
            float4 yv = *(const float4*)(sy + m * TT + t);  // broadcast
            float4 kv = *(const float4*)(sk + m * TT + t);  // broadcast
            float ad = accd[m], ac = accc[m];
            ad = fmaf(kv.x, w00, ad);
            ad = fmaf(kv.y, w01, ad);
            ad = fmaf(kv.z, w02, ad);
            ad = fmaf(kv.w, w03, ad);
            ac = fmaf(yv.x, w10, ac);
            ac = fmaf(yv.y, w11, ac);
            ac = fmaf(yv.z, w12, ac);
            ac = fmaf(yv.w, w13, ac);
            accd[m] = ad; accc[m] = ac;
        }
    }

    if (p < PP) {
        // out[b][p][2m+0] = dens, out[b][p][2m+1] = conv/(dens+1e-8)
        float4* op = (float4*)(out + ((size_t)b * PP + p) * (2 * MM));
        #pragma unroll
        for (int m = 0; m < MM; m += 2) {
            float n0 = __fdividef(accc[m],     accd[m]     + 1e-8f);
            float n1 = __fdividef(accc[m + 1], accd[m + 1] + 1e-8f);
            op[m >> 1] = make_float4(accd[m], n0, accd[m + 1], n1);
        }
    }
}

extern "C" void kernel_launch(void* const* d_in, const int* in_sizes, int n_in,
                              void* d_out, int out_size) {
    const float* y     = (const float*)d_in[0];
    const float* x     = (const float*)d_in[1];
    const int*   mask  = (const int*)  d_in[2];
    const float* sigma = (const float*)d_in[3];
    float*       out   = (float*)d_out;

    const size_t smem = (size_t)(TT + 2 * MM * TT) * sizeof(float);  // ~66 KB
    cudaFuncSetAttribute(func_repr_kernel,
                         cudaFuncAttributeMaxDynamicSharedMemorySize, (int)smem);

    dim3 grid((PP + 63) / 64, BB);
    func_repr_kernel<<<grid, 64, smem>>>(y, x, mask, sigma, out);
}

// round 2
// speedup vs baseline: 1.2074x; 1.2074x over previous
#include <cuda_runtime.h>
#include <cuda_bf16.h>

#define TT 512
#define MM 16
#define PP 600
#define BB 32

typedef unsigned long long ull;

__device__ __forceinline__ float ex2(float v) {
    float r;
    asm("ex2.approx.ftz.f32 %0, %1;" : "=f"(r) : "f"(v));
    return r;
}
__device__ __forceinline__ ull pack2(float lo, float hi) {
    ull r;
    asm("mov.b64 %0, {%1, %2};" : "=l"(r) : "f"(lo), "f"(hi));
    return r;
}
__device__ __forceinline__ void unpack2(ull v, float& lo, float& hi) {
    asm("mov.b64 {%0, %1}, %2;" : "=f"(lo), "=f"(hi) : "l"(v));
}
__device__ __forceinline__ ull fma2(ull a, ull b, ull c) {
    ull d;
    asm("fma.rn.f32x2 %0, %1, %2, %3;" : "=l"(d) : "l"(a), "l"(b), "l"(c));
    return d;
}

// smem: sx[512] floats | sky[16][512] float2 (k,y interleaved)  -> 66 KB
// reduction scratch (reuses sky region): 3 * 64 * 33 floats

__global__ __launch_bounds__(256, 3) void func_repr_kernel(
    const float* __restrict__ y, const float* __restrict__ x,
    const int*   __restrict__ mask, const float* __restrict__ sigma,
    float* __restrict__ out)
{
    extern __shared__ float sm[];
    float*  sx  = sm;                          // [TT]
    float2* sky = (float2*)(sm + TT);          // [MM][TT] (k, y)

    const int b   = blockIdx.y;
    const int tid = threadIdx.x;
    const int pl  = tid & 63;    // p-lane within 64-wide tile
    const int tq  = tid >> 6;    // t-quarter 0..3

    // ---- cooperative stage: x, and (mask->float, y) interleaved ----
    {
        const float4* xg = (const float4*)(x + (size_t)b * TT);
        if (tid < TT / 4) ((float4*)sx)[tid] = xg[tid];

        const float4* yg = (const float4*)(y    + (size_t)b * MM * TT);
        const int4*   mg = (const int4*)  (mask + (size_t)b * MM * TT);
        #pragma unroll 2
        for (int i = tid; i < MM * TT / 4; i += 256) {
            float4 yv = yg[i];
            int4   mv = mg[i];
            float4* dst = (float4*)(sky + i * 4);
            dst[0] = make_float4((float)mv.x, yv.x, (float)mv.y, yv.y);
            dst[1] = make_float4((float)mv.z, yv.z, (float)mv.w, yv.w);
        }
    }
    __syncthreads();

    const int   p = blockIdx.x * 64 + pl;
    const float g = fmaf((float)p, 50.0f / 599.0f, -1.0f);

    const float s0 = sigma[0], s1 = sigma[1];
    const float LOG2E = 1.4426950408889634f;
    const float c0 = 0.5f * LOG2E / (s0 * s0);   // exp(-d2/2s^2) == ex2(-d2*c)
    const float c1 = 0.5f * LOG2E / (s1 * s1);

    ull acc[MM];
    #pragma unroll
    for (int m = 0; m < MM; m++) acc[m] = 0ULL;

    const int t0 = tq * (TT / 4);
    for (int t = t0; t < t0 + TT / 4; t += 4) {
        float4 xv = *(const float4*)(sx + t);          // broadcast LDS.128
        float dx0 = g - xv.x, dx1 = g - xv.y, dx2 = g - xv.z, dx3 = g - xv.w;
        float d0 = dx0 * dx0, d1 = dx1 * dx1, d2 = dx2 * dx2, d3 = dx3 * dx3;
        ull wp0 = pack2(ex2(-d0 * c0), ex2(-d0 * c1));
        ull wp1 = pack2(ex2(-d1 * c0), ex2(-d1 * c1));
        ull wp2 = pack2(ex2(-d2 * c0), ex2(-d2 * c1));
        ull wp3 = pack2(ex2(-d3 * c0), ex2(-d3 * c1));

        #pragma unroll
        for (int m = 0; m < MM; m++) {
            const ulonglong2* row = (const ulonglong2*)(sky + m * TT + t);
            ulonglong2 q01 = row[0];   // pairs (k,y) for t, t+1  (broadcast)
            ulonglong2 q23 = row[1];   // pairs for t+2, t+3
            ull a = acc[m];
            a = fma2(q01.x, wp0, a);
            a = fma2(q01.y, wp1, a);
            a = fma2(q23.x, wp2, a);
            a = fma2(q23.y, wp3, a);
            acc[m] = a;
        }
    }

    // ---- cross-quarter reduction (scratch reuses sky region) ----
    float* scr = sm + TT;   // 3 * 64 * 33 floats = 25.3 KB < 64 KB
    __syncthreads();        // everyone done reading sky
    if (tq > 0) {
        float* s = scr + ((tq - 1) * 64 + pl) * 33;
        #pragma unroll
        for (int m = 0; m < MM; m++) {
            float lo, hi; unpack2(acc[m], lo, hi);
            s[2 * m]     = lo;
            s[2 * m + 1] = hi;
        }
    }
    __syncthreads();

    if (tq == 0 && p < PP) {
        const float* s0p = scr + (0 * 64 + pl) * 33;
        const float* s1p = scr + (1 * 64 + pl) * 33;
        const float* s2p = scr + (2 * 64 + pl) * 33;
        float4* op = (float4*)(out + ((size_t)b * PP + p) * (2 * MM));
        #pragma unroll
        for (int m = 0; m < MM; m += 2) {
            float dA, cA, dB, cB;
            unpack2(acc[m],     dA, cA);
            unpack2(acc[m + 1], dB, cB);
            dA += s0p[2*m]   + s1p[2*m]   + s2p[2*m];
            cA += s0p[2*m+1] + s1p[2*m+1] + s2p[2*m+1];
            dB += s0p[2*m+2] + s1p[2*m+2] + s2p[2*m+2];
            cB += s0p[2*m+3] + s1p[2*m+3] + s2p[2*m+3];
            float nA = __fdividef(cA, dA + 1e-8f);
            float nB = __fdividef(cB, dB + 1e-8f);
            op[m >> 1] = make_float4(dA, nA, dB, nB);
        }
    }
}

extern "C" void kernel_launch(void* const* d_in, const int* in_sizes, int n_in,
                              void* d_out, int out_size) {
    const float* y     = (const float*)d_in[0];
    const float* x     = (const float*)d_in[1];
    const int*   mask  = (const int*)  d_in[2];
    const float* sigma = (const float*)d_in[3];
    float*       out   = (float*)d_out;

    const size_t smem = (size_t)TT * sizeof(float)
                      + (size_t)MM * TT * sizeof(float2);   // 66 KB
    cudaFuncSetAttribute(func_repr_kernel,
                         cudaFuncAttributeMaxDynamicSharedMemorySize, (int)smem);

    dim3 grid((PP + 63) / 64, BB);
    func_repr_kernel<<<grid, 256, smem>>>(y, x, mask, sigma, out);
}

// round 3
// speedup vs baseline: 1.3962x; 1.1564x over previous
#include <cuda_runtime.h>
#include <cuda_bf16.h>

#define TT 512
#define MM 16
#define PP 600
#define BB 32

typedef unsigned long long ull;

__device__ __forceinline__ float ex2(float v) {
    float r;
    asm("ex2.approx.ftz.f32 %0, %1;" : "=f"(r) : "f"(v));
    return r;
}
__device__ __forceinline__ ull pack2(float lo, float hi) {
    ull r;
    asm("mov.b64 %0, {%1, %2};" : "=l"(r) : "f"(lo), "f"(hi));
    return r;
}
__device__ __forceinline__ void unpack2(ull v, float& lo, float& hi) {
    asm("mov.b64 {%0, %1}, %2;" : "=f"(lo), "=f"(hi) : "l"(v));
}
__device__ __forceinline__ ull fma2(ull a, ull b, ull c) {
    ull d;
    asm("fma.rn.f32x2 %0, %1, %2, %3;" : "=l"(d) : "l"(a), "l"(b), "l"(c));
    return d;
}

// smem: sx[512] | sky[16][512] float2 (k,y)  -> 66 KB
// block: 128 threads = 32 p-pair lanes x 4 t-quarters; each thread owns 2 p.

__global__ __launch_bounds__(128, 3) void func_repr_kernel(
    const float* __restrict__ y, const float* __restrict__ x,
    const int*   __restrict__ mask, const float* __restrict__ sigma,
    float* __restrict__ out)
{
    extern __shared__ float sm[];
    float*  sx  = sm;                 // [TT]
    float2* sky = (float2*)(sm + TT); // [MM][TT] (k, y)

    const int b   = blockIdx.y;
    const int tid = threadIdx.x;
    const int pl  = tid & 31;   // p-pair lane
    const int tq  = tid >> 5;   // t-quarter 0..3

    // ---- cooperative stage ----
    {
        const float4* xg = (const float4*)(x + (size_t)b * TT);
        if (tid < TT / 4) ((float4*)sx)[tid] = xg[tid];

        const float4* yg = (const float4*)(y    + (size_t)b * MM * TT);
        const int4*   mg = (const int4*)  (mask + (size_t)b * MM * TT);
        #pragma unroll 2
        for (int i = tid; i < MM * TT / 4; i += 128) {
            float4 yv = yg[i];
            int4   mv = mg[i];
            float4* dst = (float4*)(sky + i * 4);
            dst[0] = make_float4((float)mv.x, yv.x, (float)mv.y, yv.y);
            dst[1] = make_float4((float)mv.z, yv.z, (float)mv.w, yv.w);
        }
    }
    __syncthreads();

    const int p0 = blockIdx.x * 64 + pl;
    const int p1 = p0 + 32;
    const float g0 = fmaf((float)p0, 50.0f / 599.0f, -1.0f);
    const float g1 = fmaf((float)p1, 50.0f / 599.0f, -1.0f);

    const float s0 = sigma[0], s1 = sigma[1];
    const float LOG2E = 1.4426950408889634f;
    const float nc0 = -0.5f * LOG2E / (s0 * s0);
    const float nc1 = -0.5f * LOG2E / (s1 * s1);

    ull accA[MM], accB[MM];
    #pragma unroll
    for (int m = 0; m < MM; m++) { accA[m] = 0ULL; accB[m] = 0ULL; }

    const int t0 = tq * (TT / 4);
    for (int t = t0; t < t0 + TT / 4; t += 4) {
        float4 xv = *(const float4*)(sx + t);            // broadcast

        float a0 = g0 - xv.x, a1 = g0 - xv.y, a2 = g0 - xv.z, a3 = g0 - xv.w;
        float e0 = a0 * a0, e1 = a1 * a1, e2 = a2 * a2, e3 = a3 * a3;
        ull wA0 = pack2(ex2(e0 * nc0), ex2(e0 * nc1));
        ull wA1 = pack2(ex2(e1 * nc0), ex2(e1 * nc1));
        ull wA2 = pack2(ex2(e2 * nc0), ex2(e2 * nc1));
        ull wA3 = pack2(ex2(e3 * nc0), ex2(e3 * nc1));

        float b0 = g1 - xv.x, b1 = g1 - xv.y, b2 = g1 - xv.z, b3 = g1 - xv.w;
        float f0 = b0 * b0, f1 = b1 * b1, f2 = b2 * b2, f3 = b3 * b3;
        ull wB0 = pack2(ex2(f0 * nc0), ex2(f0 * nc1));
        ull wB1 = pack2(ex2(f1 * nc0), ex2(f1 * nc1));
        ull wB2 = pack2(ex2(f2 * nc0), ex2(f2 * nc1));
        ull wB3 = pack2(ex2(f3 * nc0), ex2(f3 * nc1));

        #pragma unroll
        for (int m = 0; m < MM; m++) {
            const ulonglong2* row = (const ulonglong2*)(sky + m * TT + t);
            ulonglong2 q01 = row[0];   // (k,y) for t,t+1   broadcast
            ulonglong2 q23 = row[1];   // (k,y) for t+2,t+3
            ull a = accA[m];
            a = fma2(q01.x, wA0, a);
            a = fma2(q01.y, wA1, a);
            a = fma2(q23.x, wA2, a);
            a = fma2(q23.y, wA3, a);
            accA[m] = a;
            ull c = accB[m];
            c = fma2(q01.x, wB0, c);
            c = fma2(q01.y, wB1, c);
            c = fma2(q23.x, wB2, c);
            c = fma2(q23.y, wB3, c);
            accB[m] = c;
        }
    }

    // ---- cross-quarter reduction (scratch reuses sky region) ----
    // per (quarter, lane): 64 floats at stride 67 -> conflict-free
    float* scr = sm + TT;           // 3 * 32 * 67 floats = 25.1 KB
    __syncthreads();                // done reading sky
    if (tq > 0) {
        float* s = scr + ((tq - 1) * 32 + pl) * 67;
        #pragma unroll
        for (int m = 0; m < MM; m++) {
            float lo, hi;
            unpack2(accA[m], lo, hi);
            s[2 * m] = lo; s[2 * m + 1] = hi;
            unpack2(accB[m], lo, hi);
            s[32 + 2 * m] = lo; s[32 + 2 * m + 1] = hi;
        }
    }
    __syncthreads();

    if (tq == 0) {
        const float* q1 = scr + (0 * 32 + pl) * 67;
        const float* q2 = scr + (1 * 32 + pl) * 67;
        const float* q3 = scr + (2 * 32 + pl) * 67;

        if (p0 < PP) {
            float4* op = (float4*)(out + ((size_t)p0 + (size_t)b * PP) * (2 * MM));
            #pragma unroll
            for (int m = 0; m < MM; m += 2) {
                float dA, cA, dB, cB;
                unpack2(accA[m],     dA, cA);
                unpack2(accA[m + 1], dB, cB);
                dA += q1[2*m]   + q2[2*m]   + q3[2*m];
                cA += q1[2*m+1] + q2[2*m+1] + q3[2*m+1];
                dB += q1[2*m+2] + q2[2*m+2] + q3[2*m+2];
                cB += q1[2*m+3] + q2[2*m+3] + q3[2*m+3];
                op[m >> 1] = make_float4(dA, __fdividef(cA, dA + 1e-8f),
                                         dB, __fdividef(cB, dB + 1e-8f));
            }
        }
        if (p1 < PP) {
            float4* op = (float4*)(out + ((size_t)p1 + (size_t)b * PP) * (2 * MM));
            #pragma unroll
            for (int m = 0; m < MM; m += 2) {
                float dA, cA, dB, cB;
                unpack2(accB[m],     dA, cA);
                unpack2(accB[m + 1], dB, cB);
                dA += q1[32+2*m]   + q2[32+2*m]   + q3[32+2*m];
                cA += q1[32+2*m+1] + q2[32+2*m+1] + q3[32+2*m+1];
                dB += q1[32+2*m+2] + q2[32+2*m+2] + q3[32+2*m+2];
                cB += q1[32+2*m+3] + q2[32+2*m+3] + q3[32+2*m+3];
                op[m >> 1] = make_float4(dA, __fdividef(cA, dA + 1e-8f),
                                         dB, __fdividef(cB, dB + 1e-8f));
            }
        }
    }
}

extern "C" void kernel_launch(void* const* d_in, const int* in_sizes, int n_in,
                              void* d_out, int out_size) {
    const float* y     = (const float*)d_in[0];
    const float* x     = (const float*)d_in[1];
    const int*   mask  = (const int*)  d_in[2];
    const float* sigma = (const float*)d_in[3];
    float*       out   = (float*)d_out;

    const size_t smem = (size_t)TT * sizeof(float)
                      + (size_t)MM * TT * sizeof(float2);   // 66 KB
    cudaFuncSetAttribute(func_repr_kernel,
                         cudaFuncAttributeMaxDynamicSharedMemorySize, (int)smem);

    dim3 grid((PP + 63) / 64, BB);
    func_repr_kernel<<<grid, 128, smem>>>(y, x, mask, sigma, out);
}

// round 4
// speedup vs baseline: 1.7683x; 1.2665x over previous
#include <cuda_runtime.h>
#include <cuda_bf16.h>

#define TT 512
#define MM 16
#define MH 8          // m rows per block (half)
#define PP 600
#define BB 32

typedef unsigned long long ull;

__device__ __forceinline__ float ex2(float v) {
    float r;
    asm("ex2.approx.ftz.f32 %0, %1;" : "=f"(r) : "f"(v));
    return r;
}
__device__ __forceinline__ ull pack2(float lo, float hi) {
    ull r;
    asm("mov.b64 %0, {%1, %2};" : "=l"(r) : "f"(lo), "f"(hi));
    return r;
}
__device__ __forceinline__ void unpack2(ull v, float& lo, float& hi) {
    asm("mov.b64 {%0, %1}, %2;" : "=f"(lo), "=f"(hi) : "l"(v));
}
__device__ __forceinline__ ull fma2(ull a, ull b, ull c) {
    ull d;
    asm("fma.rn.f32x2 %0, %1, %2, %3;" : "=l"(d) : "l"(a), "l"(b), "l"(c));
    return d;
}

// smem: sx[512] (pre-scaled x) | sky[8][512] float2 (k,y) -> 34 KB
// block: 128 thr = 32 p-pair lanes x 4 t-quarters; 2 p per thread, 8 m rows.
// grid: (10 p-tiles, 32 b, 2 m-halves) = 640 blocks, one wave at 5 blocks/SM.

template<bool EQ>
__device__ __forceinline__ void mainloop(
    const float* sx, const float2* sky,
    float v0, float v1, float ratio, int tq,
    ull* __restrict__ accA, ull* __restrict__ accB)
{
    const int t0 = tq * (TT / 4);
    for (int t = t0; t < t0 + TT / 4; t += 4) {
        float4 xv = *(const float4*)(sx + t);          // broadcast LDS.128

        float a0 = v0 - xv.x, a1 = v0 - xv.y, a2 = v0 - xv.z, a3 = v0 - xv.w;
        float b0 = v1 - xv.x, b1 = v1 - xv.y, b2 = v1 - xv.z, b3 = v1 - xv.w;
        float eA0 = a0 * (-a0), eA1 = a1 * (-a1), eA2 = a2 * (-a2), eA3 = a3 * (-a3);
        float eB0 = b0 * (-b0), eB1 = b1 * (-b1), eB2 = b2 * (-b2), eB3 = b3 * (-b3);

        ull wA0, wA1, wA2, wA3, wB0, wB1, wB2, wB3;
        if (EQ) {
            float w;
            w = ex2(eA0); wA0 = pack2(w, w);
            w = ex2(eA1); wA1 = pack2(w, w);
            w = ex2(eA2); wA2 = pack2(w, w);
            w = ex2(eA3); wA3 = pack2(w, w);
            w = ex2(eB0); wB0 = pack2(w, w);
            w = ex2(eB1); wB1 = pack2(w, w);
            w = ex2(eB2); wB2 = pack2(w, w);
            w = ex2(eB3); wB3 = pack2(w, w);
        } else {
            wA0 = pack2(ex2(eA0), ex2(eA0 * ratio));
            wA1 = pack2(ex2(eA1), ex2(eA1 * ratio));
            wA2 = pack2(ex2(eA2), ex2(eA2 * ratio));
            wA3 = pack2(ex2(eA3), ex2(eA3 * ratio));
            wB0 = pack2(ex2(eB0), ex2(eB0 * ratio));
            wB1 = pack2(ex2(eB1), ex2(eB1 * ratio));
            wB2 = pack2(ex2(eB2), ex2(eB2 * ratio));
            wB3 = pack2(ex2(eB3), ex2(eB3 * ratio));
        }

        #pragma unroll
        for (int m = 0; m < MH; m++) {
            const ulonglong2* row = (const ulonglong2*)(sky + m * TT + t);
            ulonglong2 q01 = row[0];   // (k,y) for t,t+1   broadcast
            ulonglong2 q23 = row[1];   // (k,y) for t+2,t+3
            ull a = accA[m];
            a = fma2(q01.x, wA0, a);
            a = fma2(q01.y, wA1, a);
            a = fma2(q23.x, wA2, a);
            a = fma2(q23.y, wA3, a);
            accA[m] = a;
            ull c = accB[m];
            c = fma2(q01.x, wB0, c);
            c = fma2(q01.y, wB1, c);
            c = fma2(q23.x, wB2, c);
            c = fma2(q23.y, wB3, c);
            accB[m] = c;
        }
    }
}

__global__ __launch_bounds__(128, 5) void func_repr_kernel(
    const float* __restrict__ y, const float* __restrict__ x,
    const int*   __restrict__ mask, const float* __restrict__ sigma,
    float* __restrict__ out)
{
    extern __shared__ float sm[];
    float*  sx  = sm;                 // [TT] pre-scaled by sqrt(c0)
    float2* sky = (float2*)(sm + TT); // [MH][TT] (k, y)

    const int b   = blockIdx.y;
    const int h   = blockIdx.z;       // m-half
    const int tid = threadIdx.x;
    const int pl  = tid & 31;
    const int tq  = tid >> 5;

    const float s0 = sigma[0], s1 = sigma[1];
    const float LOG2E = 1.4426950408889634f;
    const float rc0   = sqrtf(0.5f * LOG2E) / s0;     // sqrt(c0)
    const float ratio = (s0 * s0) / (s1 * s1);        // c1/c0

    // ---- cooperative stage ----
    {
        const float4* xg = (const float4*)(x + (size_t)b * TT);
        if (tid < TT / 4) {
            float4 xv = xg[tid];
            ((float4*)sx)[tid] = make_float4(xv.x * rc0, xv.y * rc0,
                                             xv.z * rc0, xv.w * rc0);
        }
        const float4* yg = (const float4*)(y    + ((size_t)b * MM + h * MH) * TT);
        const int4*   mg = (const int4*)  (mask + ((size_t)b * MM + h * MH) * TT);
        #pragma unroll 2
        for (int i = tid; i < MH * TT / 4; i += 128) {
            float4 yv = yg[i];
            int4   mv = mg[i];
            float4* dst = (float4*)(sky + i * 4);
            dst[0] = make_float4((float)mv.x, yv.x, (float)mv.y, yv.y);
            dst[1] = make_float4((float)mv.z, yv.z, (float)mv.w, yv.w);
        }
    }
    __syncthreads();

    const int p0 = blockIdx.x * 64 + pl;
    const int p1 = p0 + 32;
    const float v0 = rc0 * fmaf((float)p0, 50.0f / 599.0f, -1.0f);
    const float v1 = rc0 * fmaf((float)p1, 50.0f / 599.0f, -1.0f);

    ull accA[MH], accB[MH];
    #pragma unroll
    for (int m = 0; m < MH; m++) { accA[m] = 0ULL; accB[m] = 0ULL; }

    if (ratio == 1.0f)
        mainloop<true >(sx, sky, v0, v1, ratio, tq, accA, accB);
    else
        mainloop<false>(sx, sky, v0, v1, ratio, tq, accA, accB);

    // ---- cross-quarter reduction (scratch reuses sky region) ----
    float* scr = sm + TT;             // 3 * 32 * 33 floats = 12.7 KB
    __syncthreads();                  // done reading sky
    if (tq > 0) {
        float* s = scr + ((tq - 1) * 32 + pl) * 33;
        #pragma unroll
        for (int m = 0; m < MH; m++) {
            float lo, hi;
            unpack2(accA[m], lo, hi);
            s[2 * m] = lo; s[2 * m + 1] = hi;
            unpack2(accB[m], lo, hi);
            s[16 + 2 * m] = lo; s[16 + 2 * m + 1] = hi;
        }
    }
    __syncthreads();

    if (tq == 0) {
        const float* q1 = scr + (0 * 32 + pl) * 33;
        const float* q2 = scr + (1 * 32 + pl) * 33;
        const float* q3 = scr + (2 * 32 + pl) * 33;

        if (p0 < PP) {
            float4* op = (float4*)(out + ((size_t)b * PP + p0) * (2 * MM) + h * 2 * MH);
            #pragma unroll
            for (int m = 0; m < MH; m += 2) {
                float dA, cA, dB, cB;
                unpack2(accA[m],     dA, cA);
                unpack2(accA[m + 1], dB, cB);
                dA += q1[2*m]   + q2[2*m]   + q3[2*m];
                cA += q1[2*m+1] + q2[2*m+1] + q3[2*m+1];
                dB += q1[2*m+2] + q2[2*m+2] + q3[2*m+2];
                cB += q1[2*m+3] + q2[2*m+3] + q3[2*m+3];
                op[m >> 1] = make_float4(dA, __fdividef(cA, dA + 1e-8f),
                                         dB, __fdividef(cB, dB + 1e-8f));
            }
        }
        if (p1 < PP) {
            float4* op = (float4*)(out + ((size_t)b * PP + p1) * (2 * MM) + h * 2 * MH);
            #pragma unroll
            for (int m = 0; m < MH; m += 2) {
                float dA, cA, dB, cB;
                unpack2(accB[m],     dA, cA);
                unpack2(accB[m + 1], dB, cB);
                dA += q1[16+2*m]   + q2[16+2*m]   + q3[16+2*m];
                cA += q1[16+2*m+1] + q2[16+2*m+1] + q3[16+2*m+1];
                dB += q1[16+2*m+2] + q2[16+2*m+2] + q3[16+2*m+2];
                cB += q1[16+2*m+3] + q2[16+2*m+3] + q3[16+2*m+3];
                op[m >> 1] = make_float4(dA, __fdividef(cA, dA + 1e-8f),
                                         dB, __fdividef(cB, dB + 1e-8f));
            }
        }
    }
}

extern "C" void kernel_launch(void* const* d_in, const int* in_sizes, int n_in,
                              void* d_out, int out_size) {
    const float* y     = (const float*)d_in[0];
    const float* x     = (const float*)d_in[1];
    const int*   mask  = (const int*)  d_in[2];
    const float* sigma = (const float*)d_in[3];
    float*       out   = (float*)d_out;

    const size_t smem = (size_t)TT * sizeof(float)
                      + (size_t)MH * TT * sizeof(float2);   // 34 KB
    cudaFuncSetAttribute(func_repr_kernel,
                         cudaFuncAttributeMaxDynamicSharedMemorySize, (int)smem);

    dim3 grid((PP + 63) / 64, BB, 2);
    func_repr_kernel<<<grid, 128, smem>>>(y, x, mask, sigma, out);
}

// round 5
// speedup vs baseline: 3.7577x; 2.1250x over previous
#include <cuda_runtime.h>
#include <cuda_bf16.h>

#define TT 512
#define MM 16
#define MH 8
#define PP 600
#define BB 32
#define KMAX 512

typedef unsigned long long ull;

__device__ __forceinline__ float ex2(float v) {
    float r;
    asm("ex2.approx.ftz.f32 %0, %1;" : "=f"(r) : "f"(v));
    return r;
}
__device__ __forceinline__ ull pack2(float lo, float hi) {
    ull r;
    asm("mov.b64 %0, {%1, %2};" : "=l"(r) : "f"(lo), "f"(hi));
    return r;
}
__device__ __forceinline__ void unpack2(ull v, float& lo, float& hi) {
    asm("mov.b64 {%0, %1}, %2;" : "=f"(lo), "=f"(hi) : "l"(v));
}
__device__ __forceinline__ ull fma2(ull a, ull b, ull c) {
    ull d;
    asm("fma.rn.f32x2 %0, %1, %2, %3;" : "=l"(d) : "l"(a), "l"(b), "l"(c));
    return d;
}

// smem (floats):
//   [0, 512)          sxc : compacted scaled x
//   [512, 512+8192)   skyc: float2[MH][KMAX] compacted (k,y); reused as scr
//   [8704, 9216)      sidx: compacted t index (int)
//   [9216, 9224)      swsum[4], then swoff[4] at [9224,9232), K at [9232]
// total ~9240 floats = 37 KB; 5 blocks/SM.

template<bool EQ>
__device__ __forceinline__ void mainloop(
    const float* sxc, const float2* skyc, int Kp, int tq,
    float v0, float v1, float r0, float r1,
    ull* __restrict__ accA, ull* __restrict__ accB)
{
    for (int jj = 2 * tq; jj < Kp; jj += 8) {
        float2 xv = *(const float2*)(sxc + jj);        // LDS.64 broadcast
        float dA0 = v0 - xv.x, dA1 = v0 - xv.y;
        float dB0 = v1 - xv.x, dB1 = v1 - xv.y;
        float eA0 = dA0 * (-dA0), eA1 = dA1 * (-dA1);
        float eB0 = dB0 * (-dB0), eB1 = dB1 * (-dB1);

        ull wA0, wA1, wB0, wB1;
        if (EQ) {
            float w;
            w = ex2(eA0); wA0 = pack2(w, w);
            w = ex2(eA1); wA1 = pack2(w, w);
            w = ex2(eB0); wB0 = pack2(w, w);
            w = ex2(eB1); wB1 = pack2(w, w);
        } else {
            wA0 = pack2(ex2(eA0 * r0), ex2(eA0 * r1));
            wA1 = pack2(ex2(eA1 * r0), ex2(eA1 * r1));
            wB0 = pack2(ex2(eB0 * r0), ex2(eB0 * r1));
            wB1 = pack2(ex2(eB1 * r0), ex2(eB1 * r1));
        }

        #pragma unroll
        for (int m = 0; m < MH; m++) {
            ulonglong2 q = *(const ulonglong2*)(skyc + m * KMAX + jj); // LDS.128
            accA[m] = fma2(q.y, wA1, fma2(q.x, wA0, accA[m]));
            accB[m] = fma2(q.y, wB1, fma2(q.x, wB0, accB[m]));
        }
    }
}

__global__ __launch_bounds__(128, 5) void func_repr_kernel(
    const float* __restrict__ y, const float* __restrict__ x,
    const int*   __restrict__ mask, const float* __restrict__ sigma,
    float* __restrict__ out)
{
    extern __shared__ float sm[];
    float*  sxc  = sm;
    float2* skyc = (float2*)(sm + 512);
    int*    sidx = (int*)(sm + 8704);
    int*    swsum = (int*)(sm + 9216);
    int*    swoff = (int*)(sm + 9224);
    int*    sK    = (int*)(sm + 9232);

    const int b    = blockIdx.y;
    const int h    = blockIdx.z;
    const int tid  = threadIdx.x;
    const int lane = tid & 31;
    const int wrp  = tid >> 5;
    const int pl   = tid & 31;
    const int tq   = tid >> 5;

    const float s0 = sigma[0], s1 = sigma[1];
    const float LOG2E = 1.4426950408889634f;
    const float smax  = fmaxf(s0, s1);
    const float rcmin = sqrtf(0.5f * LOG2E) / smax;     // sqrt(c_min)
    const float r0 = (smax / s0) * (smax / s0);         // c0/cmin >= 1
    const float r1 = (smax / s1) * (smax / s1);         // c1/cmin >= 1

    const int   pfirst = blockIdx.x * 64;
    const float gA = fmaf((float)pfirst,        50.0f / 599.0f, -1.0f);
    const float gZ = fmaf((float)(pfirst + 63), 50.0f / 599.0f, -1.0f);
    const float vlo = rcmin * gA - 6.7f;   // 6.7^2=44.9 -> weight <= 3e-14
    const float vhi = rcmin * gZ + 6.7f;

    // ---- deterministic compaction of x into [vlo, vhi] ----
    float4 xv4 = ((const float4*)(x + (size_t)b * TT))[tid];  // t = 4*tid..+3
    float vv[4] = { xv4.x * rcmin, xv4.y * rcmin, xv4.z * rcmin, xv4.w * rcmin };
    int pass = 0, cnt = 0;
    #pragma unroll
    for (int k = 0; k < 4; k++) {
        bool in = (vv[k] >= vlo) & (vv[k] <= vhi);
        pass |= (int)in << k;
        cnt  += (int)in;
    }
    int incl = cnt;
    #pragma unroll
    for (int o = 1; o < 32; o <<= 1) {
        int n = __shfl_up_sync(0xFFFFFFFFu, incl, o);
        if (lane >= o) incl += n;
    }
    if (lane == 31) swsum[wrp] = incl;
    __syncthreads();
    if (tid == 0) {
        int s = 0;
        #pragma unroll
        for (int w = 0; w < 4; w++) { int t = swsum[w]; swoff[w] = s; s += t; }
        *sK = s;
    }
    __syncthreads();
    {
        int pos = swoff[wrp] + incl - cnt;
        #pragma unroll
        for (int k = 0; k < 4; k++) {
            if ((pass >> k) & 1) {
                sxc[pos]  = vv[k];
                sidx[pos] = tid * 4 + k;
                pos++;
            }
        }
    }
    __syncthreads();

    const int K  = *sK;
    const int Kp = (K + 7) & ~7;
    if (tid < Kp - K) sxc[K + tid] = 1.0e9f;   // sentinel -> weight 0

    // ---- gather compacted (k, y) rows from global (L2) ----
    const float* yb = y    + ((size_t)b * MM + h * MH) * TT;
    const int*   mb = mask + ((size_t)b * MM + h * MH) * TT;
    for (int i = tid; i < Kp * MH; i += 128) {
        int j = i >> 3, m = i & 7;
        float2 kv;
        if (j < K) {
            int t = sidx[j];
            kv = make_float2((float)mb[m * TT + t], yb[m * TT + t]);
        } else {
            kv = make_float2(0.f, 0.f);
        }
        skyc[m * KMAX + j] = kv;
    }
    __syncthreads();

    const int p0 = pfirst + pl;
    const int p1 = p0 + 32;
    const float v0 = rcmin * fmaf((float)p0, 50.0f / 599.0f, -1.0f);
    const float v1 = rcmin * fmaf((float)p1, 50.0f / 599.0f, -1.0f);

    ull accA[MH], accB[MH];
    #pragma unroll
    for (int m = 0; m < MH; m++) { accA[m] = 0ULL; accB[m] = 0ULL; }

    if (s0 == s1)
        mainloop<true >(sxc, skyc, Kp, tq, v0, v1, r0, r1, accA, accB);
    else
        mainloop<false>(sxc, skyc, Kp, tq, v0, v1, r0, r1, accA, accB);

    // ---- cross-quarter reduction (scratch overlays skyc) ----
    float* scr = sm + 512;            // 3 * 32 * 33 = 3168 floats
    __syncthreads();                  // done reading skyc
    if (tq > 0) {
        float* s = scr + ((tq - 1) * 32 + pl) * 33;
        #pragma unroll
        for (int m = 0; m < MH; m++) {
            float lo, hi;
            unpack2(accA[m], lo, hi);
            s[2 * m] = lo; s[2 * m + 1] = hi;
            unpack2(accB[m], lo, hi);
            s[16 + 2 * m] = lo; s[16 + 2 * m + 1] = hi;
        }
    }
    __syncthreads();

    if (tq == 0) {
        const float* q1 = scr + (0 * 32 + pl) * 33;
        const float* q2 = scr + (1 * 32 + pl) * 33;
        const float* q3 = scr + (2 * 32 + pl) * 33;

        if (p0 < PP) {
            float4* op = (float4*)(out + ((size_t)b * PP + p0) * (2 * MM) + h * 2 * MH);
            #pragma unroll
            for (int m = 0; m < MH; m += 2) {
                float dA, cA, dB, cB;
                unpack2(accA[m],     dA, cA);
                unpack2(accA[m + 1], dB, cB);
                dA += q1[2*m]   + q2[2*m]   + q3[2*m];
                cA += q1[2*m+1] + q2[2*m+1] + q3[2*m+1];
                dB += q1[2*m+2] + q2[2*m+2] + q3[2*m+2];
                cB += q1[2*m+3] + q2[2*m+3] + q3[2*m+3];
                op[m >> 1] = make_float4(dA, __fdividef(cA, dA + 1e-8f),
                                         dB, __fdividef(cB, dB + 1e-8f));
            }
        }
        if (p1 < PP) {
            float4* op = (float4*)(out + ((size_t)b * PP + p1) * (2 * MM) + h * 2 * MH);
            #pragma unroll
            for (int m = 0; m < MH; m += 2) {
                float dA, cA, dB, cB;
                unpack2(accB[m],     dA, cA);
                unpack2(accB[m + 1], dB, cB);
                dA += q1[16+2*m]   + q2[16+2*m]   + q3[16+2*m];
                cA += q1[16+2*m+1] + q2[16+2*m+1] + q3[16+2*m+1];
                dB += q1[16+2*m+2] + q2[16+2*m+2] + q3[16+2*m+2];
                cB += q1[16+2*m+3] + q2[16+2*m+3] + q3[16+2*m+3];
                op[m >> 1] = make_float4(dA, __fdividef(cA, dA + 1e-8f),
                                         dB, __fdividef(cB, dB + 1e-8f));
            }
        }
    }
}

extern "C" void kernel_launch(void* const* d_in, const int* in_sizes, int n_in,
                              void* d_out, int out_size) {
    const float* y     = (const float*)d_in[0];
    const float* x     = (const float*)d_in[1];
    const int*   mask  = (const int*)  d_in[2];
    const float* sigma = (const float*)d_in[3];
    float*       out   = (float*)d_out;

    const size_t smem = 9240 * sizeof(float);   // ~37 KB
    cudaFuncSetAttribute(func_repr_kernel,
                         cudaFuncAttributeMaxDynamicSharedMemorySize, (int)smem);

    dim3 grid((PP + 63) / 64, BB, 2);
    func_repr_kernel<<<grid, 128, smem>>>(y, x, mask, sigma, out);
}

// round 6
// speedup vs baseline: 3.8260x; 1.0182x over previous
#include <cuda_runtime.h>
#include <cuda_bf16.h>

#define TT 512
#define MM 16
#define MH 8
#define PP 600
#define BB 32
#define KMAX 512

typedef unsigned long long ull;

__device__ __forceinline__ float ex2(float v) {
    float r;
    asm("ex2.approx.ftz.f32 %0, %1;" : "=f"(r) : "f"(v));
    return r;
}
__device__ __forceinline__ ull pack2(float lo, float hi) {
    ull r;
    asm("mov.b64 %0, {%1, %2};" : "=l"(r) : "f"(lo), "f"(hi));
    return r;
}
__device__ __forceinline__ void unpack2(ull v, float& lo, float& hi) {
    asm("mov.b64 {%0, %1}, %2;" : "=f"(lo), "=f"(hi) : "l"(v));
}
__device__ __forceinline__ ull fma2(ull a, ull b, ull c) {
    ull d;
    asm("fma.rn.f32x2 %0, %1, %2, %3;" : "=l"(d) : "l"(a), "l"(b), "l"(c));
    return d;
}

// smem (floats):
//   [0, 512)          sxc : compacted scaled x (+ sentinels)
//   [512, 8704)       skyc: float2[MH][KMAX] compacted (k,y); reused as scr
//   [8704, 9216)      sidx: compacted t index (int)
//   [9216, 9220)      swsum[4]
// total 9220 floats = 36.9 KB; target 6 blocks/SM.

template<bool EQ>
__device__ __forceinline__ void mainloop(
    const float* sxc, const float2* skyc, int Kp, int tq,
    float v0, float v1, float r0, float r1,
    ull* __restrict__ accA, ull* __restrict__ accB)
{
    for (int jj = 2 * tq; jj < Kp; jj += 8) {
        float2 xv = *(const float2*)(sxc + jj);        // LDS.64 broadcast
        float dA0 = v0 - xv.x, dA1 = v0 - xv.y;
        float dB0 = v1 - xv.x, dB1 = v1 - xv.y;
        float eA0 = dA0 * (-dA0), eA1 = dA1 * (-dA1);
        float eB0 = dB0 * (-dB0), eB1 = dB1 * (-dB1);

        ull wA0, wA1, wB0, wB1;
        if (EQ) {
            float w;
            w = ex2(eA0); wA0 = pack2(w, w);
            w = ex2(eA1); wA1 = pack2(w, w);
            w = ex2(eB0); wB0 = pack2(w, w);
            w = ex2(eB1); wB1 = pack2(w, w);
        } else {
            wA0 = pack2(ex2(eA0 * r0), ex2(eA0 * r1));
            wA1 = pack2(ex2(eA1 * r0), ex2(eA1 * r1));
            wB0 = pack2(ex2(eB0 * r0), ex2(eB0 * r1));
            wB1 = pack2(ex2(eB1 * r0), ex2(eB1 * r1));
        }

        #pragma unroll
        for (int m = 0; m < MH; m++) {
            ulonglong2 q = *(const ulonglong2*)(skyc + m * KMAX + jj); // LDS.128
            accA[m] = fma2(q.y, wA1, fma2(q.x, wA0, accA[m]));
            accB[m] = fma2(q.y, wB1, fma2(q.x, wB0, accB[m]));
        }
    }
}

__global__ __launch_bounds__(128, 6) void func_repr_kernel(
    const float* __restrict__ y, const float* __restrict__ x,
    const int*   __restrict__ mask, const float* __restrict__ sigma,
    float* __restrict__ out)
{
    extern __shared__ float sm[];
    float*  sxc   = sm;
    float2* skyc  = (float2*)(sm + 512);
    int*    sidx  = (int*)(sm + 8704);
    int*    swsum = (int*)(sm + 9216);

    const int b    = blockIdx.y;
    const int h    = blockIdx.z;
    const int tid  = threadIdx.x;
    const int lane = tid & 31;
    const int wrp  = tid >> 5;
    const int pl   = lane;
    const int tq   = wrp;

    const float s0 = sigma[0], s1 = sigma[1];
    const float LOG2E = 1.4426950408889634f;
    const float smax  = fmaxf(s0, s1);
    const float rcmin = sqrtf(0.5f * LOG2E) / smax;     // sqrt(c_min)
    const float r0 = (smax / s0) * (smax / s0);
    const float r1 = (smax / s1) * (smax / s1);

    const int   pfirst = blockIdx.x * 64;
    const float gA = fmaf((float)pfirst,        50.0f / 599.0f, -1.0f);
    const float gZ = fmaf((float)(pfirst + 63), 50.0f / 599.0f, -1.0f);
    const float vlo = rcmin * gA - 6.7f;   // 6.7^2=44.9 -> dropped weight <= 3e-14
    const float vhi = rcmin * gZ + 6.7f;

    // ---- deterministic compaction of x into [vlo, vhi] ----
    float4 xv4 = ((const float4*)(x + (size_t)b * TT))[tid];  // t = 4*tid..+3
    float vv[4] = { xv4.x * rcmin, xv4.y * rcmin, xv4.z * rcmin, xv4.w * rcmin };
    int pass = 0, cnt = 0;
    #pragma unroll
    for (int k = 0; k < 4; k++) {
        bool in = (vv[k] >= vlo) & (vv[k] <= vhi);
        pass |= (int)in << k;
        cnt  += (int)in;
    }
    int incl = cnt;
    #pragma unroll
    for (int o = 1; o < 32; o <<= 1) {
        int n = __shfl_up_sync(0xFFFFFFFFu, incl, o);
        if (lane >= o) incl += n;
    }
    if (lane == 31) swsum[wrp] = incl;
    __syncthreads();

    // every thread computes the warp-prefix redundantly (broadcast LDS)
    int w0 = swsum[0], w1 = swsum[1], w2 = swsum[2], w3 = swsum[3];
    int woff = (wrp > 0 ? w0 : 0) + (wrp > 1 ? w1 : 0) + (wrp > 2 ? w2 : 0);
    const int K  = w0 + w1 + w2 + w3;
    const int Kp = (K + 7) & ~7;

    {
        int pos = woff + incl - cnt;
        #pragma unroll
        for (int k = 0; k < 4; k++) {
            if ((pass >> k) & 1) {
                sxc[pos]  = vv[k];
                sidx[pos] = tid * 4 + k;
                pos++;
            }
        }
    }
    if (tid < Kp - K) sxc[K + tid] = 1.0e9f;   // sentinel -> weight 0
    __syncthreads();

    // ---- ordered, coalesced gather: warp-per-row, lanes take consecutive j ----
    const float* yb = y    + ((size_t)b * MM + h * MH) * TT;
    const int*   mb = mask + ((size_t)b * MM + h * MH) * TT;
    #pragma unroll
    for (int m = wrp; m < MH; m += 4) {
        const int*   mrow = mb + m * TT;
        const float* yrow = yb + m * TT;
        for (int j = lane; j < Kp; j += 32) {
            float2 kv;
            if (j < K) {
                int t = sidx[j];
                kv = make_float2((float)__ldg(mrow + t), __ldg(yrow + t));
            } else {
                kv = make_float2(0.f, 0.f);
            }
            skyc[m * KMAX + j] = kv;
        }
    }
    __syncthreads();

    const int p0 = pfirst + pl;
    const int p1 = p0 + 32;
    const float v0 = rcmin * fmaf((float)p0, 50.0f / 599.0f, -1.0f);
    const float v1 = rcmin * fmaf((float)p1, 50.0f / 599.0f, -1.0f);

    ull accA[MH], accB[MH];
    #pragma unroll
    for (int m = 0; m < MH; m++) { accA[m] = 0ULL; accB[m] = 0ULL; }

    if (s0 == s1)
        mainloop<true >(sxc, skyc, Kp, tq, v0, v1, r0, r1, accA, accB);
    else
        mainloop<false>(sxc, skyc, Kp, tq, v0, v1, r0, r1, accA, accB);

    // ---- cross-quarter reduction (scratch overlays skyc) ----
    float* scr = sm + 512;            // 3 * 32 * 33 = 3168 floats
    __syncthreads();                  // done reading skyc
    if (tq > 0) {
        float* s = scr + ((tq - 1) * 32 + pl) * 33;
        #pragma unroll
        for (int m = 0; m < MH; m++) {
            float lo, hi;
            unpack2(accA[m], lo, hi);
            s[2 * m] = lo; s[2 * m + 1] = hi;
            unpack2(accB[m], lo, hi);
            s[16 + 2 * m] = lo; s[16 + 2 * m + 1] = hi;
        }
    }
    __syncthreads();

    if (tq == 0) {
        const float* q1 = scr + (0 * 32 + pl) * 33;
        const float* q2 = scr + (1 * 32 + pl) * 33;
        const float* q3 = scr + (2 * 32 + pl) * 33;

        if (p0 < PP) {
            float4* op = (float4*)(out + ((size_t)b * PP + p0) * (2 * MM) + h * 2 * MH);
            #pragma unroll
            for (int m = 0; m < MH; m += 2) {
                float dA, cA, dB, cB;
                unpack2(accA[m],     dA, cA);
                unpack2(accA[m + 1], dB, cB);
                dA += q1[2*m]   + q2[2*m]   + q3[2*m];
                cA += q1[2*m+1] + q2[2*m+1] + q3[2*m+1];
                dB += q1[2*m+2] + q2[2*m+2] + q3[2*m+2];
                cB += q1[2*m+3] + q2[2*m+3] + q3[2*m+3];
                op[m >> 1] = make_float4(dA, __fdividef(cA, dA + 1e-8f),
                                         dB, __fdividef(cB, dB + 1e-8f));
            }
        }
        if (p1 < PP) {
            float4* op = (float4*)(out + ((size_t)b * PP + p1) * (2 * MM) + h * 2 * MH);
            #pragma unroll
            for (int m = 0; m < MH; m += 2) {
                float dA, cA, dB, cB;
                unpack2(accB[m],     dA, cA);
                unpack2(accB[m + 1], dB, cB);
                dA += q1[16+2*m]   + q2[16+2*m]   + q3[16+2*m];
                cA += q1[16+2*m+1] + q2[16+2*m+1] + q3[16+2*m+1];
                dB += q1[16+2*m+2] + q2[16+2*m+2] + q3[16+2*m+2];
                cB += q1[16+2*m+3] + q2[16+2*m+3] + q3[16+2*m+3];
                op[m >> 1] = make_float4(dA, __fdividef(cA, dA + 1e-8f),
                                         dB, __fdividef(cB, dB + 1e-8f));
            }
        }
    }
}

extern "C" void kernel_launch(void* const* d_in, const int* in_sizes, int n_in,
                              void* d_out, int out_size) {
    const float* y     = (const float*)d_in[0];
    const float* x     = (const float*)d_in[1];
    const int*   mask  = (const int*)  d_in[2];
    const float* sigma = (const float*)d_in[3];
    float*       out   = (float*)d_out;

    const size_t smem = 9220 * sizeof(float);   // 36.9 KB
    cudaFuncSetAttribute(func_repr_kernel,
                         cudaFuncAttributeMaxDynamicSharedMemorySize, (int)smem);

    dim3 grid((PP + 63) / 64, BB, 2);
    func_repr_kernel<<<grid, 128, smem>>>(y, x, mask, sigma, out);
}